// round 3
// baseline (speedup 1.0000x reference)
#include <cuda_runtime.h>

// BoxModelTriples: M=8 mixture components, D=32 dims, boxes (M,B,2,D) f32,
// ids (N,4) int32 (jax x64-disabled downcasts int64->int32), output (N,) f32.
//
// One warp per query n. lane = m*4 + q, m = lane>>2 in [0,8),
// q = lane&3 selects dims [q*8, q*8+8). Each thread loads 8 dims of the
// z-side and Z-side of boxes A(i0), B(i1), C(i2) for its m via float4,
// accumulates per-thread partial products of clipped side lengths, then:
//   - product-reduce over q (xor 1,2)                  -> vol per (m)
//   - weight by softmax w[m], sum over m (xor 4,8,16)  -> weighted sums
// 15 shuffles per query. All gathers are 256B-aligned contiguous rows.

#define TINYF 1.17549435e-38f

__device__ float g_w[8];

__global__ void softmax8_kernel(const float* __restrict__ w, int m) {
    int lane = threadIdx.x & 31;
    float x = (lane < m) ? w[lane] : -3.0e38f;
    float mx = x;
    #pragma unroll
    for (int off = 16; off; off >>= 1)
        mx = fmaxf(mx, __shfl_xor_sync(0xFFFFFFFFu, mx, off));
    float e = (lane < m) ? expf(x - mx) : 0.0f;
    float s = e;
    #pragma unroll
    for (int off = 16; off; off >>= 1)
        s += __shfl_xor_sync(0xFFFFFFFFu, s, off);
    if (lane < m) g_w[lane] = e / s;
}

__device__ __forceinline__ void side_step(float az, float aZ,
                                          float bz, float bZ,
                                          float cz, float cZ,
                                          float& pA, float& pAB, float& pABC) {
    float a0 = __saturatef(az), a1 = __saturatef(aZ);
    float b0 = __saturatef(bz), b1 = __saturatef(bZ);
    float c0 = __saturatef(cz), c1 = __saturatef(cZ);
    pA *= fmaxf(a1 - a0, 0.0f);
    float z = fmaxf(a0, b0);
    float Z = fminf(a1, b1);
    pAB *= fmaxf(Z - z, 0.0f);
    z = fmaxf(z, c0);
    Z = fminf(Z, c1);
    pABC *= fmaxf(Z - z, 0.0f);
}

__device__ __forceinline__ void quad_step(float4 az, float4 aZ,
                                          float4 bz, float4 bZ,
                                          float4 cz, float4 cZ,
                                          float& pA, float& pAB, float& pABC) {
    side_step(az.x, aZ.x, bz.x, bZ.x, cz.x, cZ.x, pA, pAB, pABC);
    side_step(az.y, aZ.y, bz.y, bZ.y, cz.y, cZ.y, pA, pAB, pABC);
    side_step(az.z, aZ.z, bz.z, bZ.z, cz.z, cZ.z, pA, pAB, pABC);
    side_step(az.w, aZ.w, bz.w, bZ.w, cz.w, cZ.w, pA, pAB, pABC);
}

__global__ void __launch_bounds__(256)
triples_kernel(const float* __restrict__ box,
               const int* __restrict__ ids,
               float* __restrict__ out,
               int N, int B) {
    int lane = threadIdx.x & 31;
    int n = blockIdx.x * (blockDim.x >> 5) + (threadIdx.x >> 5);
    if (n >= N) return;

    const int* idp = ids + 4 * n;
    int i0 = idp[0];
    int i1 = idp[1];
    int i2 = idp[2];

    int m = lane >> 2;      // 0..7
    int q = lane & 3;       // 0..3, dims [q*8, q*8+8)

    size_t mb = (size_t)m * (size_t)B;
    const float* pAp = box + (mb + (size_t)i0) * 64 + q * 8;
    const float* pBp = box + (mb + (size_t)i1) * 64 + q * 8;
    const float* pCp = box + (mb + (size_t)i2) * 64 + q * 8;

    // z-side at +0, Z-side at +32 floats within the 64-float (m, idx) row.
    float4 az0 = *(const float4*)(pAp);
    float4 az1 = *(const float4*)(pAp + 4);
    float4 aZ0 = *(const float4*)(pAp + 32);
    float4 aZ1 = *(const float4*)(pAp + 36);
    float4 bz0 = *(const float4*)(pBp);
    float4 bz1 = *(const float4*)(pBp + 4);
    float4 bZ0 = *(const float4*)(pBp + 32);
    float4 bZ1 = *(const float4*)(pBp + 36);
    float4 cz0 = *(const float4*)(pCp);
    float4 cz1 = *(const float4*)(pCp + 4);
    float4 cZ0 = *(const float4*)(pCp + 32);
    float4 cZ1 = *(const float4*)(pCp + 36);

    float pA = 1.0f, pAB = 1.0f, pABC = 1.0f;
    quad_step(az0, aZ0, bz0, bZ0, cz0, cZ0, pA, pAB, pABC);
    quad_step(az1, aZ1, bz1, bZ1, cz1, cZ1, pA, pAB, pABC);

    // Product-reduce over the 4 q-lanes within each m group (xor 1, 2).
    #pragma unroll
    for (int off = 1; off <= 2; off <<= 1) {
        pA   *= __shfl_xor_sync(0xFFFFFFFFu, pA,   off);
        pAB  *= __shfl_xor_sync(0xFFFFFFFFu, pAB,  off);
        pABC *= __shfl_xor_sync(0xFFFFFFFFu, pABC, off);
    }

    // Weight and sum over the 8 m groups (xor 4, 8, 16).
    float wm = g_w[m];
    float sA = wm * pA, sAB = wm * pAB, sABC = wm * pABC;
    #pragma unroll
    for (int off = 4; off <= 16; off <<= 1) {
        sA   += __shfl_xor_sync(0xFFFFFFFFu, sA,   off);
        sAB  += __shfl_xor_sync(0xFFFFFFFFu, sAB,  off);
        sABC += __shfl_xor_sync(0xFFFFFFFFu, sABC, off);
    }

    if (lane == 0) {
        float res;
        if (i1 != i2) {
            res = (sABC + TINYF) / (sAB + TINYF);      // three_cond
        } else if (i0 == i1) {
            res = sA;                                   // unary
        } else {
            res = (sAB + TINYF) / (sA + TINYF);         // two_cond
        }
        out[n] = res;
    }
}

extern "C" void kernel_launch(void* const* d_in, const int* in_sizes, int n_in,
                              void* d_out, int out_size) {
    const float* box = (const float*)d_in[0];
    const float* w   = (const float*)d_in[1];
    const int*   ids = (const int*)d_in[2];
    float*       out = (float*)d_out;

    int Mw = in_sizes[1];                 // 8
    int N  = in_sizes[2] / 4;             // 100000
    int B  = (int)((long long)in_sizes[0] / ((long long)Mw * 64));  // 200000

    softmax8_kernel<<<1, 32>>>(w, Mw);

    const int warps_per_block = 8;        // 256 threads
    int blocks = (N + warps_per_block - 1) / warps_per_block;
    triples_kernel<<<blocks, warps_per_block * 32>>>(box, ids, out, N, B);
}

// round 4
// speedup vs baseline: 1.4082x; 1.4082x over previous
#include <cuda_runtime.h>

// BoxModelTriples, m-phased for L2 residency.
// box: (M=8, B=200000, 2, D=32) f32 -> 64 floats (256 B) per (m, idx) row,
//      z at +0, Z at +128 B. Each m-slab is B*256B = 51.2 MB < 126 MB L2.
// ids: (N, 4) int32. out: (N,) f32.
//
// Kernel 1: softmax over 8 weights -> g_w.
// Kernel 2 (phase): blockIdx.y = m (slow raster dim => slab-phased execution).
//   warp = 4 queries; per query 8 lanes, 4 dims each. Lane loads float4 z/Z
//   for A,B,C (6x LDG.128), partial products, xor-reduce over 8 lanes,
//   writes w[m]*{volA, volAB, volABC} to partial buffer (deterministic).
// Kernel 3 (reduce): sum 8 m-partials per query, apply mask logic, write out.

#define TINYF 1.17549435e-38f
#define MAXN  100096

__device__ float g_w[8];
__device__ float g_P[3 * 8 * MAXN];   // [(c*8 + m)*N + n]

__global__ void softmax8_kernel(const float* __restrict__ w, int m) {
    int lane = threadIdx.x & 31;
    float x = (lane < m) ? w[lane] : -3.0e38f;
    float mx = x;
    #pragma unroll
    for (int off = 16; off; off >>= 1)
        mx = fmaxf(mx, __shfl_xor_sync(0xFFFFFFFFu, mx, off));
    float e = (lane < m) ? expf(x - mx) : 0.0f;
    float s = e;
    #pragma unroll
    for (int off = 16; off; off >>= 1)
        s += __shfl_xor_sync(0xFFFFFFFFu, s, off);
    if (lane < m) g_w[lane] = e / s;
}

__device__ __forceinline__ void side_step(float az, float aZ,
                                          float bz, float bZ,
                                          float cz, float cZ,
                                          float& pA, float& pAB, float& pABC) {
    float a0 = __saturatef(az), a1 = __saturatef(aZ);
    float b0 = __saturatef(bz), b1 = __saturatef(bZ);
    float c0 = __saturatef(cz), c1 = __saturatef(cZ);
    pA *= fmaxf(a1 - a0, 0.0f);
    float z = fmaxf(a0, b0);
    float Z = fminf(a1, b1);
    pAB *= fmaxf(Z - z, 0.0f);
    z = fmaxf(z, c0);
    Z = fminf(Z, c1);
    pABC *= fmaxf(Z - z, 0.0f);
}

__global__ void __launch_bounds__(256)
phase_kernel(const float* __restrict__ box,
             const int* __restrict__ ids,
             int N, int B) {
    int m    = blockIdx.y;                       // slow raster dim -> phased
    int lane = threadIdx.x & 31;
    int warp = threadIdx.x >> 5;                 // 0..7
    int qq   = lane >> 3;                        // query within warp, 0..3
    int d    = lane & 7;                         // dim group, dims [4d, 4d+4)

    int n = (blockIdx.x * 8 + warp) * 4 + qq;
    int nc = n < N ? n : N - 1;                  // clamp loads, predicate store

    int4 id = *(const int4*)(ids + 4 * nc);

    size_t mb = (size_t)m * (size_t)B;
    const float* pAp = box + (mb + (size_t)id.x) * 64 + d * 4;
    const float* pBp = box + (mb + (size_t)id.y) * 64 + d * 4;
    const float* pCp = box + (mb + (size_t)id.z) * 64 + d * 4;

    float4 az = *(const float4*)(pAp);
    float4 aZ = *(const float4*)(pAp + 32);
    float4 bz = *(const float4*)(pBp);
    float4 bZ = *(const float4*)(pBp + 32);
    float4 cz = *(const float4*)(pCp);
    float4 cZ = *(const float4*)(pCp + 32);

    float pA = 1.0f, pAB = 1.0f, pABC = 1.0f;
    side_step(az.x, aZ.x, bz.x, bZ.x, cz.x, cZ.x, pA, pAB, pABC);
    side_step(az.y, aZ.y, bz.y, bZ.y, cz.y, cZ.y, pA, pAB, pABC);
    side_step(az.z, aZ.z, bz.z, bZ.z, cz.z, cZ.z, pA, pAB, pABC);
    side_step(az.w, aZ.w, bz.w, bZ.w, cz.w, cZ.w, pA, pAB, pABC);

    // Product-reduce across the 8 dim-lanes of this query (xor 1, 2, 4).
    #pragma unroll
    for (int off = 1; off <= 4; off <<= 1) {
        pA   *= __shfl_xor_sync(0xFFFFFFFFu, pA,   off);
        pAB  *= __shfl_xor_sync(0xFFFFFFFFu, pAB,  off);
        pABC *= __shfl_xor_sync(0xFFFFFFFFu, pABC, off);
    }

    if (d == 0 && n < N) {
        float wm = g_w[m];
        size_t mN = (size_t)m * N + n;
        g_P[0 * 8 * (size_t)N + mN] = wm * pA;
        g_P[1 * 8 * (size_t)N + mN] = wm * pAB;
        g_P[2 * 8 * (size_t)N + mN] = wm * pABC;
    }
}

__global__ void __launch_bounds__(256)
reduce_kernel(const int* __restrict__ ids,
              float* __restrict__ out, int N) {
    int n = blockIdx.x * blockDim.x + threadIdx.x;
    if (n >= N) return;

    float sA = 0.0f, sAB = 0.0f, sABC = 0.0f;
    #pragma unroll
    for (int m = 0; m < 8; m++) {
        size_t mN = (size_t)m * N + n;
        sA   += g_P[0 * 8 * (size_t)N + mN];
        sAB  += g_P[1 * 8 * (size_t)N + mN];
        sABC += g_P[2 * 8 * (size_t)N + mN];
    }

    const int* idp = ids + 4 * n;
    int i0 = idp[0], i1 = idp[1], i2 = idp[2];

    float res;
    if (i1 != i2) {
        res = (sABC + TINYF) / (sAB + TINYF);      // three_cond
    } else if (i0 == i1) {
        res = sA;                                   // unary
    } else {
        res = (sAB + TINYF) / (sA + TINYF);         // two_cond
    }
    out[n] = res;
}

extern "C" void kernel_launch(void* const* d_in, const int* in_sizes, int n_in,
                              void* d_out, int out_size) {
    const float* box = (const float*)d_in[0];
    const float* w   = (const float*)d_in[1];
    const int*   ids = (const int*)d_in[2];
    float*       out = (float*)d_out;

    int Mw = in_sizes[1];                 // 8
    int N  = in_sizes[2] / 4;             // 100000
    int B  = (int)((long long)in_sizes[0] / ((long long)Mw * 64));  // 200000

    softmax8_kernel<<<1, 32>>>(w, Mw);

    // 32 queries per block (8 warps x 4 queries), m on grid.y (slow).
    int chunks = (N + 31) / 32;
    phase_kernel<<<dim3(chunks, 8), 256>>>(box, ids, N, B);

    reduce_kernel<<<(N + 255) / 256, 256>>>(ids, out, N);
}

// round 5
// speedup vs baseline: 1.4664x; 1.0413x over previous
#include <cuda_runtime.h>

// BoxModelTriples, m-phased for L2 residency (two kernels, no softmax launch).
// box: (M=8, B=200000, 2, D=32) f32 -> 64 floats (256 B) per (m, idx) row,
//      z at +0, Z at +128 B. Each m-slab is B*256B = 51.2 MB < 126 MB L2.
// ids: (N, 4) int32. out: (N,) f32.
//
// Kernel 1 (phase): blockIdx.y = m (slow raster dim => slab-phased execution
//   so each 51.2 MB slab becomes L2-resident while being gathered).
//   warp = 4 queries; per query 8 lanes, 4 dims each. Lane loads float4 z/Z
//   for A,B,C (6x LDG.128), partial products, xor-reduce over 8 lanes,
//   writes UNWEIGHTED {volA, volAB, volABC} as one float4 per (m, n).
// Kernel 2 (reduce): computes softmax(w) inline, weighted-sums the 8
//   m-partials per query, applies mask logic, writes out.

#define TINYF 1.17549435e-38f
#define MAXN  100096

__device__ float4 g_P[8 * MAXN];   // [m * N + n] = {volA, volAB, volABC, 0}

__device__ __forceinline__ void side_step(float az, float aZ,
                                          float bz, float bZ,
                                          float cz, float cZ,
                                          float& pA, float& pAB, float& pABC) {
    float a0 = __saturatef(az), a1 = __saturatef(aZ);
    float b0 = __saturatef(bz), b1 = __saturatef(bZ);
    float c0 = __saturatef(cz), c1 = __saturatef(cZ);
    pA *= fmaxf(a1 - a0, 0.0f);
    float z = fmaxf(a0, b0);
    float Z = fminf(a1, b1);
    pAB *= fmaxf(Z - z, 0.0f);
    z = fmaxf(z, c0);
    Z = fminf(Z, c1);
    pABC *= fmaxf(Z - z, 0.0f);
}

__global__ void __launch_bounds__(256)
phase_kernel(const float* __restrict__ box,
             const int* __restrict__ ids,
             int N, int B) {
    int m    = blockIdx.y;                       // slow raster dim -> phased
    int lane = threadIdx.x & 31;
    int warp = threadIdx.x >> 5;                 // 0..7
    int qq   = lane >> 3;                        // query within warp, 0..3
    int d    = lane & 7;                         // dim group, dims [4d, 4d+4)

    int n = (blockIdx.x * 8 + warp) * 4 + qq;
    int nc = n < N ? n : N - 1;                  // clamp loads, predicate store

    int4 id = *(const int4*)(ids + 4 * nc);

    size_t mb = (size_t)m * (size_t)B;
    const float* pAp = box + (mb + (size_t)id.x) * 64 + d * 4;
    const float* pBp = box + (mb + (size_t)id.y) * 64 + d * 4;
    const float* pCp = box + (mb + (size_t)id.z) * 64 + d * 4;

    float4 az = *(const float4*)(pAp);
    float4 aZ = *(const float4*)(pAp + 32);
    float4 bz = *(const float4*)(pBp);
    float4 bZ = *(const float4*)(pBp + 32);
    float4 cz = *(const float4*)(pCp);
    float4 cZ = *(const float4*)(pCp + 32);

    float pA = 1.0f, pAB = 1.0f, pABC = 1.0f;
    side_step(az.x, aZ.x, bz.x, bZ.x, cz.x, cZ.x, pA, pAB, pABC);
    side_step(az.y, aZ.y, bz.y, bZ.y, cz.y, cZ.y, pA, pAB, pABC);
    side_step(az.z, aZ.z, bz.z, bZ.z, cz.z, cZ.z, pA, pAB, pABC);
    side_step(az.w, aZ.w, bz.w, bZ.w, cz.w, cZ.w, pA, pAB, pABC);

    // Product-reduce across the 8 dim-lanes of this query (xor 1, 2, 4).
    #pragma unroll
    for (int off = 1; off <= 4; off <<= 1) {
        pA   *= __shfl_xor_sync(0xFFFFFFFFu, pA,   off);
        pAB  *= __shfl_xor_sync(0xFFFFFFFFu, pAB,  off);
        pABC *= __shfl_xor_sync(0xFFFFFFFFu, pABC, off);
    }

    if (d == 0 && n < N) {
        g_P[(size_t)m * N + n] = make_float4(pA, pAB, pABC, 0.0f);
    }
}

__global__ void __launch_bounds__(256)
reduce_kernel(const float* __restrict__ w,
              const int* __restrict__ ids,
              float* __restrict__ out, int N) {
    int n = blockIdx.x * blockDim.x + threadIdx.x;
    if (n >= N) return;

    // Inline softmax over the 8 weights (L1-broadcast loads, trivial cost).
    float wv[8];
    float mx = -3.0e38f;
    #pragma unroll
    for (int m = 0; m < 8; m++) { wv[m] = w[m]; mx = fmaxf(mx, wv[m]); }
    float s = 0.0f;
    #pragma unroll
    for (int m = 0; m < 8; m++) { wv[m] = expf(wv[m] - mx); s += wv[m]; }
    float inv = 1.0f / s;

    float sA = 0.0f, sAB = 0.0f, sABC = 0.0f;
    #pragma unroll
    for (int m = 0; m < 8; m++) {
        float4 p = g_P[(size_t)m * N + n];
        float wm = wv[m] * inv;
        sA   += wm * p.x;
        sAB  += wm * p.y;
        sABC += wm * p.z;
    }

    int4 id = *(const int4*)(ids + 4 * n);

    float res;
    if (id.y != id.z) {
        res = (sABC + TINYF) / (sAB + TINYF);      // three_cond
    } else if (id.x == id.y) {
        res = sA;                                   // unary
    } else {
        res = (sAB + TINYF) / (sA + TINYF);         // two_cond
    }
    out[n] = res;
}

extern "C" void kernel_launch(void* const* d_in, const int* in_sizes, int n_in,
                              void* d_out, int out_size) {
    const float* box = (const float*)d_in[0];
    const float* w   = (const float*)d_in[1];
    const int*   ids = (const int*)d_in[2];
    float*       out = (float*)d_out;

    int Mw = in_sizes[1];                 // 8
    int N  = in_sizes[2] / 4;             // 100000
    int B  = (int)((long long)in_sizes[0] / ((long long)Mw * 64));  // 200000

    // 32 queries per block (8 warps x 4 queries), m on grid.y (slow).
    int chunks = (N + 31) / 32;
    phase_kernel<<<dim3(chunks, 8), 256>>>(box, ids, N, B);

    reduce_kernel<<<(N + 255) / 256, 256>>>(w, ids, out, N);
}